// round 11
// baseline (speedup 1.0000x reference)
#include <cuda_runtime.h>

// KAN 3x3 convolution, single channel, uniform cubic B-spline (G=5, s=3, h=0.4).
// x in [0,1) -> knot interval j in {5,6,7}; 4 active bases placed in 6 slots (c=2..7).
// Phase 1: per input pixel g_p = silu(x)*bw[p] + sum_s m_s*sw[p][s+2], 9 taps p=(a,b).
//          The 6-wide dot is computed as packed f32x2 pairs: feature pairs (m0,m1),
//          (m2,m3),(m4,m5) in GPR pairs; weight pairs (w2,w3),(w4,w5),(w6,w7) are
//          contiguous 8B-aligned in __constant__ -> LDCU.64 uniform pairs.
//          Planes stored SHIFTED by -b so phase 2 reads one column.
// Phase 2: out(h, w..w+3) = sum over 9 planes of one aligned float4 (LDS.128 + f32x2 adds).

#define TW 64
#define TH 16
#define IW (TW + 2)          // 66
#define IH (TH + 2)          // 18
#define GPAD 68              // padded row stride (floats); 272B rows keep 16B alignment
#define PS (IH * GPAD)       // plane stride = 1224 floats
#define NPIX (IH * IW)       // 1188
#define NTHREADS 256
#define NITER ((NPIX + NTHREADS - 1) / NTHREADS)   // 5
#define WIDTH 256
#define HO 254
#define WO 254

typedef unsigned long long ull;

#define PACK2(d, lo, hi)   asm("mov.b64 %0, {%1, %2};" : "=l"(d) : "f"(lo), "f"(hi))
#define UNPACK2(lo, hi, s) asm("mov.b64 {%0, %1}, %2;" : "=f"(lo), "=f"(hi) : "l"(s))
#define FMA2(d, a, b, c)   asm("fma.rn.f32x2 %0, %1, %2, %3;" : "=l"(d) : "l"(a), "l"(b), "l"(c))
#define MUL2(d, a, b)      asm("mul.rn.f32x2 %0, %1, %2;" : "=l"(d) : "l"(a), "l"(b))
#define ADD2(d, a, b)      asm("add.rn.f32x2 %0, %1, %2;" : "=l"(d) : "l"(a), "l"(b))
#define RCPA(d, a)         asm("rcp.approx.f32 %0, %1;" : "=f"(d) : "f"(a))

__constant__ float cSW[72];    // spline weights, [9][8]

__global__ void __launch_bounds__(NTHREADS, 5)
kan_conv_kernel(const float* __restrict__ X,
                const float* __restrict__ BWg,
                float* __restrict__ OUT)
{
    // +8 floats: shifted halo writes (col' up to 69 on the last plane/row) stay in-bounds.
    __shared__ __align__(16) float gs[9 * PS + 8];   // 44096 B

    const int tid = threadIdx.x;
    const int w0  = blockIdx.x * TW;
    const int h0  = blockIdx.y * TH;
    const float* Xi = X + (size_t)blockIdx.z * (WIDTH * WIDTH);

    // base weights -> 9 regs (hoisted LDG, block-uniform broadcast hits)
    float BW[9];
#pragma unroll
    for (int p = 0; p < 9; ++p) BW[p] = __ldg(BWg + p);

    // constant space viewed as 8B pairs: index p*4+1 -> (w[p][2],w[p][3]), etc.
    const ull* W2 = (const ull*)cSW;

    // ---------------- Phase 1 ----------------
    // front-batched global loads (MLP = NITER) + precomputed smem base offsets
    float xv[NITER];
    int   sb[NITER];
#pragma unroll
    for (int it = 0; it < NITER; ++it) {
        int i  = tid + it * NTHREADS;
        int ii = (i < NPIX) ? i : 0;
        int r  = ii / IW;
        int c  = ii - r * IW;
        sb[it] = r * GPAD + c + 4;               // plane p writes sb - (p%3)
        int gr = min(h0 + r, WIDTH - 1);
        int gc = min(w0 + c, WIDTH - 1);
        xv[it] = __ldg(Xi + gr * WIDTH + gc);
    }

#pragma unroll
    for (int it = 0; it < NITER; ++it) {
        float x = xv[it];

        float y  = fmaf(x, 2.5f, 5.5f);          // (x + 2.2) / 0.4  -> [5.5, 8.0)
        float jf = floorf(y);                    // in {5,6,7}
        jf = fminf(jf, 7.0f);                    // guards x -> 1^- rounding to 8.0
        float u  = y - jf;

        const float c16 = 0.16666666666666666f;
        float omu = 1.0f - u;
        float u2  = u * u;
        float n0 = omu * omu * omu * c16;
        float n3 = u2 * u * c16;
        float n1 = fmaf(u2, fmaf(0.5f, u, -1.0f), 0.6666666666666666f);
        float n2 = 1.0f - n0 - n1 - n3;          // partition of unity

        bool j0 = (jf == 5.0f), j1 = (jf == 6.0f);
        float m0 = j0 ? n0 : 0.0f;
        float m1 = j0 ? n1 : (j1 ? n0 : 0.0f);
        float m2 = j0 ? n2 : (j1 ? n1 : n0);
        float m3 = j0 ? n3 : (j1 ? n2 : n1);
        float m4 = j0 ? 0.0f : (j1 ? n3 : n2);
        float m5 = (j0 || j1) ? 0.0f : n3;

        // silu(x) = x * rcp(1 + e^{-x})
        float e = __expf(-x);
        float inv; RCPA(inv, 1.0f + e);
        float s = x * inv;

        // feature pairs for the packed dot products
        ull F01, F23, F45;
        PACK2(F01, m0, m1);
        PACK2(F23, m2, m3);
        PACK2(F45, m4, m5);

        if (tid + it * NTHREADS < NPIX) {
            float* base = gs + sb[it];
#pragma unroll
            for (int p = 0; p < 9; ++p) {
                ull acc;
                MUL2(acc, F45, W2[p * 4 + 3]);        // (m4*w6, m5*w7)
                FMA2(acc, F23, W2[p * 4 + 2], acc);   // += (m2*w4, m3*w5)
                FMA2(acc, F01, W2[p * 4 + 1], acc);   // += (m0*w2, m1*w3)
                float lo, hi;
                UNPACK2(lo, hi, acc);
                float g = fmaf(s, BW[p], lo + hi);
                base[p * PS - (p % 3)] = g;
            }
        }
    }
    __syncthreads();

    // ---------------- Phase 2: 4 outputs/thread, 9 aligned 16B smem loads ----
    const int lw4 = (tid & 15) * 4;
    const int lh  = tid >> 4;
    const int h   = h0 + lh;

    if (h < HO) {
        const char* rbase = (const char*)(gs + lh * GPAD + lw4 + 4);
        ulonglong2 v0 = *(const ulonglong2*)(rbase);
        ull alo = v0.x, ahi = v0.y;
#pragma unroll
        for (int a = 0; a < 3; ++a)
#pragma unroll
            for (int b = 0; b < 3; ++b) {
                if (a == 0 && b == 0) continue;
                ulonglong2 v = *(const ulonglong2*)(rbase +
                        ((a * 3 + b) * PS + a * GPAD) * sizeof(float));
                ADD2(alo, alo, v.x);
                ADD2(ahi, ahi, v.y);
            }

        const int w = w0 + lw4;
        float* op = OUT + (size_t)blockIdx.z * (HO * WO) + (size_t)h * WO + w;
        if (w + 3 < WO) {
            *(ull*)(op)     = alo;
            *(ull*)(op + 2) = ahi;
        } else {
            float f0, f1, f2, f3;
            UNPACK2(f0, f1, alo);
            UNPACK2(f2, f3, ahi);
            if (w     < WO) op[0] = f0;
            if (w + 1 < WO) op[1] = f1;
            if (w + 2 < WO) op[2] = f2;
            if (w + 3 < WO) op[3] = f3;
        }
    }
}

extern "C" void kernel_launch(void* const* d_in, const int* in_sizes, int n_in,
                              void* d_out, int out_size)
{
    const float* x  = (const float*)d_in[0];
    const float* bw = (const float*)d_in[1];
    float* out = (float*)d_out;

    // Stage spline weights into __constant__ (one D2D async copy, graph-capturable).
    cudaMemcpyToSymbolAsync(cSW, d_in[2], 72 * sizeof(float), 0,
                            cudaMemcpyDeviceToDevice, 0);

    int batch = in_sizes[0] / (WIDTH * WIDTH);   // 32
    dim3 grid((WO + TW - 1) / TW, (HO + TH - 1) / TH, batch);
    kan_conv_kernel<<<grid, NTHREADS>>>(x, bw, out);
}

// round 14
// speedup vs baseline: 1.0017x; 1.0017x over previous
#include <cuda_runtime.h>

// KAN 3x3 convolution, single channel, uniform cubic B-spline (G=5, s=3, h=0.4).
// x in [0,1) -> knot interval j in {5,6,7}; 4 active bases placed in 6 slots (c=2..7).
// Phase 1: per input pixel g_p = silu(x)*bw[p] + sum_s m_s*sw[p][s+2], 9 taps p=(a,b);
//          spline weights in __constant__ (LDCU -> uniform regs), base weights via
//          __ldg (9 GPRs). Planes stored SHIFTED by -b so phase 2 reads one column.
//          Tail-peeled iteration + interior fast-path (no clamp) loads.
// Phase 2: out(h, w..w+3) = sum over 9 planes of one aligned float4 (LDS.128 + f32x2 adds).

#define TW 64
#define TH 16
#define IW (TW + 2)          // 66
#define IH (TH + 2)          // 18
#define GPAD 68              // padded row stride (floats); 272B rows keep 16B alignment
#define PS (IH * GPAD)       // plane stride = 1224 floats
#define NPIX (IH * IW)       // 1188
#define NTHREADS 256
#define NFULL (NPIX / NTHREADS)                    // 4 full iterations
#define WIDTH 256
#define HO 254
#define WO 254

typedef unsigned long long ull;

#define UNPACK2(lo, hi, s) asm("mov.b64 {%0, %1}, %2;" : "=f"(lo), "=f"(hi) : "l"(s))
#define ADD2(d, a, b)      asm("add.rn.f32x2 %0, %1, %2;" : "=l"(d) : "l"(a), "l"(b))
#define RCPA(d, a)         asm("rcp.approx.f32 %0, %1;" : "=f"(d) : "f"(a))

__constant__ float cSW[72];    // spline weights, [9][8]

// per-pixel evaluation: features + 9 tap dots, store to shifted planes
__device__ __forceinline__ void eval_store(float x, int sbase, float* gs,
                                           const float* BW)
{
    float y  = fmaf(x, 2.5f, 5.5f);          // (x + 2.2) / 0.4  -> [5.5, 8.0)
    float jf = floorf(y);                    // in {5,6,7}
    float u  = y - jf;

    const float c16 = 0.16666666666666666f;
    float omu = 1.0f - u;
    float u2  = u * u;
    float n0 = omu * omu * omu * c16;
    float n3 = u2 * u * c16;
    float n1 = fmaf(u2, fmaf(0.5f, u, -1.0f), 0.6666666666666666f);
    float n2 = 1.0f - n0 - n1 - n3;          // partition of unity

    bool j0 = (jf == 5.0f), j1 = (jf == 6.0f);
    float m0 = j0 ? n0 : 0.0f;
    float m1 = j0 ? n1 : (j1 ? n0 : 0.0f);
    float m2 = j0 ? n2 : (j1 ? n1 : n0);
    float m3 = j0 ? n3 : (j1 ? n2 : n1);
    float m4 = j0 ? 0.0f : (j1 ? n3 : n2);
    float m5 = (j0 || j1) ? 0.0f : n3;

    // silu(x) = x * rcp(1 + e^{-x})
    float e = __expf(-x);
    float inv; RCPA(inv, 1.0f + e);
    float s = x * inv;

    float* base = gs + sbase;
#pragma unroll
    for (int p = 0; p < 9; ++p) {
        float g = s * BW[p];
        g = fmaf(m0, cSW[p * 8 + 2], g);
        g = fmaf(m1, cSW[p * 8 + 3], g);
        g = fmaf(m2, cSW[p * 8 + 4], g);
        g = fmaf(m3, cSW[p * 8 + 5], g);
        g = fmaf(m4, cSW[p * 8 + 6], g);
        g = fmaf(m5, cSW[p * 8 + 7], g);
        base[p * PS - (p % 3)] = g;
    }
}

__global__ void __launch_bounds__(NTHREADS, 5)
kan_conv_kernel(const float* __restrict__ X,
                const float* __restrict__ BWg,
                float* __restrict__ OUT)
{
    // +8 floats: shifted halo writes (col' up to 69 on the last plane/row) stay in-bounds.
    __shared__ __align__(16) float gs[9 * PS + 8];   // 44096 B

    const int tid = threadIdx.x;
    const int w0  = blockIdx.x * TW;
    const int h0  = blockIdx.y * TH;
    const float* Xi = X + (size_t)blockIdx.z * (WIDTH * WIDTH);

    // base weights -> 9 regs (hoisted LDG, block-uniform broadcast hits)
    float BW[9];
#pragma unroll
    for (int p = 0; p < 9; ++p) BW[p] = __ldg(BWg + p);

    // ---------------- Phase 1 ----------------
    // front-batched global loads (MLP = 5) + precomputed smem base offsets
    const bool interior = (w0 + IW <= WIDTH) && (h0 + IH <= WIDTH);

    float xv[NFULL + 1];
    int   sb[NFULL + 1];
#pragma unroll
    for (int it = 0; it <= NFULL; ++it) {
        int i  = tid + it * NTHREADS;
        int ii = (i < NPIX) ? i : 0;
        int r  = ii / IW;
        int c  = ii - r * IW;
        sb[it] = r * GPAD + c + 4;               // plane p writes sb - (p%3)
        if (interior) {
            xv[it] = __ldg(Xi + (h0 + r) * WIDTH + w0 + c);
        } else {
            int gr = min(h0 + r, WIDTH - 1);
            int gc = min(w0 + c, WIDTH - 1);
            xv[it] = __ldg(Xi + gr * WIDTH + gc);
        }
    }

#pragma unroll
    for (int it = 0; it < NFULL; ++it)           // 1024 pixels, unguarded
        eval_store(xv[it], sb[it], gs, BW);

    if (tid + NFULL * NTHREADS < NPIX)           // 164-pixel tail; idle warps skip
        eval_store(xv[NFULL], sb[NFULL], gs, BW);

    __syncthreads();

    // ---------------- Phase 2: 4 outputs/thread, 9 aligned 16B smem loads ----
    const int lw4 = (tid & 15) * 4;
    const int lh  = tid >> 4;
    const int h   = h0 + lh;

    if (h < HO) {
        const char* rbase = (const char*)(gs + lh * GPAD + lw4 + 4);
        ulonglong2 v0 = *(const ulonglong2*)(rbase);
        ull alo = v0.x, ahi = v0.y;
#pragma unroll
        for (int a = 0; a < 3; ++a)
#pragma unroll
            for (int b = 0; b < 3; ++b) {
                if (a == 0 && b == 0) continue;
                ulonglong2 v = *(const ulonglong2*)(rbase +
                        ((a * 3 + b) * PS + a * GPAD) * sizeof(float));
                ADD2(alo, alo, v.x);
                ADD2(ahi, ahi, v.y);
            }

        const int w = w0 + lw4;
        float* op = OUT + (size_t)blockIdx.z * (HO * WO) + (size_t)h * WO + w;
        if (w + 3 < WO) {
            *(ull*)(op)     = alo;
            *(ull*)(op + 2) = ahi;
        } else {
            float f0, f1, f2, f3;
            UNPACK2(f0, f1, alo);
            UNPACK2(f2, f3, ahi);
            if (w     < WO) op[0] = f0;
            if (w + 1 < WO) op[1] = f1;
            if (w + 2 < WO) op[2] = f2;
            if (w + 3 < WO) op[3] = f3;
        }
    }
}

extern "C" void kernel_launch(void* const* d_in, const int* in_sizes, int n_in,
                              void* d_out, int out_size)
{
    const float* x  = (const float*)d_in[0];
    const float* bw = (const float*)d_in[1];
    float* out = (float*)d_out;

    // Stage spline weights into __constant__ (one D2D async copy, graph-capturable).
    cudaMemcpyToSymbolAsync(cSW, d_in[2], 72 * sizeof(float), 0,
                            cudaMemcpyDeviceToDevice, 0);

    int batch = in_sizes[0] / (WIDTH * WIDTH);   // 32
    dim3 grid((WO + TW - 1) / TW, (HO + TH - 1) / TH, batch);
    kan_conv_kernel<<<grid, NTHREADS>>>(x, bw, out);
}